// round 13
// baseline (speedup 1.0000x reference)
#include <cuda_runtime.h>
#include <cstdint>

// out[i] = x[i] + 42.0f, 8192*4096 fp32. HBM mixed-stream bound (~90% spec).
// R13: clean A/B on the 5x-reproduced floor config — only CTA width changes.
// TPB 256->512, UNR 8->4: identical tile (2048 f4/block), grid (4096),
// instruction stream, and cache ops; halves CTAs/SM at fixed MLP.

constexpr int TPB = 512;
constexpr int UNR = 4;                       // float4 per thread
constexpr int TILE = TPB * UNR;              // float4 per block = 2048 (unchanged)

__global__ void __launch_bounds__(TPB) add42_exact(const float4* __restrict__ in,
                                                   float4* __restrict__ out) {
    const unsigned base = blockIdx.x * TILE + threadIdx.x;
    float4 v[UNR];
    #pragma unroll
    for (int k = 0; k < UNR; k++)
        v[k] = __ldcs(&in[base + k * TPB]);   // evict-first: no reuse
    #pragma unroll
    for (int k = 0; k < UNR; k++) {
        v[k].x += 42.0f; v[k].y += 42.0f; v[k].z += 42.0f; v[k].w += 42.0f;
        __stcs(&out[base + k * TPB], v[k]);   // streaming store
    }
}

// Grid-stride float4 fallback for remainder after exact tiles.
__global__ void __launch_bounds__(256) add42_vec4_gs(const float4* __restrict__ in,
                                                     float4* __restrict__ out,
                                                     long long start, long long n4) {
    const long long stride = (long long)gridDim.x * blockDim.x;
    for (long long i = start + (long long)blockIdx.x * blockDim.x + threadIdx.x;
         i < n4; i += stride) {
        float4 a = __ldcs(&in[i]);
        a.x += 42.0f; a.y += 42.0f; a.z += 42.0f; a.w += 42.0f;
        __stcs(&out[i], a);
    }
}

__global__ void add42_tail(const float* __restrict__ in, float* __restrict__ out,
                           long long start, long long n) {
    long long i = start + (long long)blockIdx.x * blockDim.x + threadIdx.x;
    if (i < n) out[i] = in[i] + 42.0f;
}

extern "C" void kernel_launch(void* const* d_in, const int* in_sizes, int n_in,
                              void* d_out, int out_size) {
    const float* x = (const float*)d_in[0];
    float* out = (float*)d_out;
    const long long n = (long long)in_sizes[0];

    const long long n4 = n / 4;
    const long long exact_blocks = n4 / TILE;           // 4096 for 8192x4096
    if (exact_blocks > 0) {
        add42_exact<<<(int)exact_blocks, TPB>>>((const float4*)x, (float4*)out);
    }
    const long long vec_rem_start = exact_blocks * (long long)TILE;
    if (vec_rem_start < n4) {
        long long rem = n4 - vec_rem_start;
        int blocks = (int)((rem + 255) / 256);
        if (blocks > 152 * 8) blocks = 152 * 8;
        add42_vec4_gs<<<blocks, 256>>>((const float4*)x, (float4*)out,
                                       vec_rem_start, n4);
    }
    const long long tail_start = n4 * 4;
    if (tail_start < n) {
        long long tail = n - tail_start;
        int blocks = (int)((tail + 127) / 128);
        add42_tail<<<blocks, 128>>>(x, out, tail_start, n);
    }
}

// round 14
// speedup vs baseline: 1.0409x; 1.0409x over previous
#include <cuda_runtime.h>
#include <cstdint>

// out[i] = x[i] + 42.0f, 8192*4096 fp32. FINAL kernel.
// Floor config, reproduced 5x at 43.5-43.8us e2e: float4 x8 per thread,
// TPB=256, exact 32KB tiles, .cs load/store.
//
// 13-round sweep, all alternatives 0.9-2.1us slower or neutral:
//   vector width 128/256b | per-thread MLP 4-16 (8 optimal: covers 577cyc
//   DRAM latency; halving it cost 2.1us at R13) | occupancy 29/58/73% |
//   cache ops .ca/.cs/.cg | L2 evict_last full+partial (hints don't create
//   cross-replay residency on sm_103a) | read/write burst phasing.
// Physics: 268.4MB mandatory DRAM/replay (no reuse, working set 268MB > 126MB
// L2) at ~7.3TB/s effective = ~90% of 8TB/s HBM3e mixed-stream spec. SMs idle
// (issue 5%). ~6.7us fixed graph-replay overhead. This is the roofline.

constexpr int TPB = 256;
constexpr int UNR = 8;                       // float4 per thread
constexpr int TILE = TPB * UNR;              // float4 per block = 2048

__global__ void __launch_bounds__(TPB) add42_exact(const float4* __restrict__ in,
                                                   float4* __restrict__ out) {
    const unsigned base = blockIdx.x * TILE + threadIdx.x;
    float4 v[UNR];
    #pragma unroll
    for (int k = 0; k < UNR; k++)
        v[k] = __ldcs(&in[base + k * TPB]);   // evict-first: no reuse
    #pragma unroll
    for (int k = 0; k < UNR; k++) {
        v[k].x += 42.0f; v[k].y += 42.0f; v[k].z += 42.0f; v[k].w += 42.0f;
        __stcs(&out[base + k * TPB], v[k]);   // streaming store
    }
}

// Grid-stride float4 fallback for remainder after exact tiles (not launched
// for the 8192x4096 shape; kept for generality/correctness on any n).
__global__ void __launch_bounds__(TPB) add42_vec4_gs(const float4* __restrict__ in,
                                                     float4* __restrict__ out,
                                                     long long start, long long n4) {
    const long long stride = (long long)gridDim.x * blockDim.x;
    for (long long i = start + (long long)blockIdx.x * blockDim.x + threadIdx.x;
         i < n4; i += stride) {
        float4 a = __ldcs(&in[i]);
        a.x += 42.0f; a.y += 42.0f; a.z += 42.0f; a.w += 42.0f;
        __stcs(&out[i], a);
    }
}

__global__ void add42_tail(const float* __restrict__ in, float* __restrict__ out,
                           long long start, long long n) {
    long long i = start + (long long)blockIdx.x * blockDim.x + threadIdx.x;
    if (i < n) out[i] = in[i] + 42.0f;
}

extern "C" void kernel_launch(void* const* d_in, const int* in_sizes, int n_in,
                              void* d_out, int out_size) {
    const float* x = (const float*)d_in[0];
    float* out = (float*)d_out;
    const long long n = (long long)in_sizes[0];

    const long long n4 = n / 4;
    const long long exact_blocks = n4 / TILE;           // 4096 for 8192x4096
    if (exact_blocks > 0) {
        add42_exact<<<(int)exact_blocks, TPB>>>((const float4*)x, (float4*)out);
    }
    const long long vec_rem_start = exact_blocks * (long long)TILE;
    if (vec_rem_start < n4) {
        long long rem = n4 - vec_rem_start;
        int blocks = (int)((rem + TPB - 1) / TPB);
        if (blocks > 152 * 8) blocks = 152 * 8;
        add42_vec4_gs<<<blocks, TPB>>>((const float4*)x, (float4*)out,
                                       vec_rem_start, n4);
    }
    const long long tail_start = n4 * 4;
    if (tail_start < n) {
        long long tail = n - tail_start;
        int blocks = (int)((tail + 127) / 128);
        add42_tail<<<blocks, 128>>>(x, out, tail_start, n);
    }
}

// round 15
// speedup vs baseline: 1.0417x; 1.0007x over previous
#include <cuda_runtime.h>
#include <cstdint>

// out[i] = x[i] + 42.0f, 8192*4096 fp32. FINAL kernel — converged.
// Floor config, reproduced 6x at 43.5-43.8us e2e (mean 43.65, sigma 0.15):
// float4 x8 per thread, TPB=256, exact 32KB tiles, .cs load/store.
//
// 14-round sweep; every neighboring config measured 0.3-2.1us slower:
//   MLP 4/8/16 (8 optimal — covers 577cyc DRAM latency without shrinking
//   concurrent CTA count) | vector 128/256b | occupancy 29-88% | cache ops
//   .ca/.cs/.cg | L2 evict_last full+partial (no cross-replay residency on
//   sm_103a) | read/write burst phasing.
// Physics: 268.4MB mandatory DRAM traffic/replay at ~7.35TB/s effective
// (~92% of 8TB/s HBM3e mixed-stream spec, turnaround-limited). SMs 95% idle.
// ~6.7us fixed graph-replay overhead outside kernel control. Roofline reached.

constexpr int TPB = 256;
constexpr int UNR = 8;                       // float4 per thread
constexpr int TILE = TPB * UNR;              // float4 per block = 2048

__global__ void __launch_bounds__(TPB) add42_exact(const float4* __restrict__ in,
                                                   float4* __restrict__ out) {
    const unsigned base = blockIdx.x * TILE + threadIdx.x;
    float4 v[UNR];
    #pragma unroll
    for (int k = 0; k < UNR; k++)
        v[k] = __ldcs(&in[base + k * TPB]);   // evict-first: no reuse
    #pragma unroll
    for (int k = 0; k < UNR; k++) {
        v[k].x += 42.0f; v[k].y += 42.0f; v[k].z += 42.0f; v[k].w += 42.0f;
        __stcs(&out[base + k * TPB], v[k]);   // streaming store
    }
}

// Grid-stride float4 fallback for remainder after exact tiles (not launched
// for the 8192x4096 shape; kept for generality/correctness on any n).
__global__ void __launch_bounds__(TPB) add42_vec4_gs(const float4* __restrict__ in,
                                                     float4* __restrict__ out,
                                                     long long start, long long n4) {
    const long long stride = (long long)gridDim.x * blockDim.x;
    for (long long i = start + (long long)blockIdx.x * blockDim.x + threadIdx.x;
         i < n4; i += stride) {
        float4 a = __ldcs(&in[i]);
        a.x += 42.0f; a.y += 42.0f; a.z += 42.0f; a.w += 42.0f;
        __stcs(&out[i], a);
    }
}

__global__ void add42_tail(const float* __restrict__ in, float* __restrict__ out,
                           long long start, long long n) {
    long long i = start + (long long)blockIdx.x * blockDim.x + threadIdx.x;
    if (i < n) out[i] = in[i] + 42.0f;
}

extern "C" void kernel_launch(void* const* d_in, const int* in_sizes, int n_in,
                              void* d_out, int out_size) {
    const float* x = (const float*)d_in[0];
    float* out = (float*)d_out;
    const long long n = (long long)in_sizes[0];

    const long long n4 = n / 4;
    const long long exact_blocks = n4 / TILE;           // 4096 for 8192x4096
    if (exact_blocks > 0) {
        add42_exact<<<(int)exact_blocks, TPB>>>((const float4*)x, (float4*)out);
    }
    const long long vec_rem_start = exact_blocks * (long long)TILE;
    if (vec_rem_start < n4) {
        long long rem = n4 - vec_rem_start;
        int blocks = (int)((rem + TPB - 1) / TPB);
        if (blocks > 152 * 8) blocks = 152 * 8;
        add42_vec4_gs<<<blocks, TPB>>>((const float4*)x, (float4*)out,
                                       vec_rem_start, n4);
    }
    const long long tail_start = n4 * 4;
    if (tail_start < n) {
        long long tail = n - tail_start;
        int blocks = (int)((tail + 127) / 128);
        add42_tail<<<blocks, 128>>>(x, out, tail_start, n);
    }
}